// round 3
// baseline (speedup 1.0000x reference)
#include <cuda_runtime.h>
#include <math.h>

// ----------------------------------------------------------------------------
// AUGGCN: 2-layer GCN + linear head + sigmoid
//   deg/dinv -> xw = x@W1 -> scatter1(norm) +b1,relu -> @W2 -> scatter2(norm)
//   -> +b2,relu -> @Wc+bc -> sigmoid
// Edge-index dtype (int32 vs int64) detected at runtime on-device.
// ----------------------------------------------------------------------------

#define MAXN 100000
#define FDIM 165
#define H1DIM 128
#define H2DIM 2

// Scratch (device globals; no allocations allowed)
__device__ __align__(16) float g_deg[MAXN];
__device__ __align__(16) float g_dinv[MAXN];
__device__ __align__(16) float g_xw[(size_t)MAXN * H1DIM];   // x @ W1
__device__ __align__(16) float g_h1[(size_t)MAXN * H1DIM];   // scatter accum L1
__device__ __align__(16) float g_h2w[(size_t)MAXN * H2DIM];  // relu(h1+b1) @ W2
__device__ __align__(16) float g_h2[(size_t)MAXN * H2DIM];   // scatter accum L2
__device__ int g_is64;                                        // edge dtype flag

// ---------------- edge-index access (dtype-agnostic) ------------------------
__device__ __forceinline__ int edge_at(const void* ei, long long pos, int is64) {
    if (is64) return (int)((const long long*)ei)[pos];
    return ((const int*)ei)[pos];
}

// ---------------- vector global reductions (sm_90+) -------------------------
__device__ __forceinline__ void red_add_v4(float* p, float4 v) {
    asm volatile("red.global.add.v4.f32 [%0], {%1,%2,%3,%4};"
                 :: "l"(p), "f"(v.x), "f"(v.y), "f"(v.z), "f"(v.w) : "memory");
}
__device__ __forceinline__ void red_add_v2(float* p, float a, float b) {
    asm volatile("red.global.add.v2.f32 [%0], {%1,%2};"
                 :: "l"(p), "f"(a), "f"(b) : "memory");
}

// ---------------- init: zero accum, deg=1 (self loop), dtype detect ---------
// int64 little-endian with values < 2^31: every odd 32-bit word is 0.
// int32: odd words are random node ids; 64 consecutive zeros ~ impossible.
__global__ void k_init(const int* __restrict__ ei32, int n) {
    long long i = (long long)blockIdx.x * blockDim.x + threadIdx.x;
    if (i == 0) {
        int all_zero = 1;
#pragma unroll 8
        for (int t = 0; t < 64; t++)
            if (ei32[2 * t + 1] != 0) { all_zero = 0; break; }
        g_is64 = all_zero;
    }
    long long tot = (long long)n * H1DIM;
    if (i < tot) g_h1[i] = 0.f;
    if (i < (long long)n * H2DIM) g_h2[i] = 0.f;
    if (i < n) g_deg[i] = 1.0f;   // self loop contributes 1 to dst degree
}

// ---------------- degree over edges -----------------------------------------
__global__ void k_degree(const void* __restrict__ ei, int E) {
    int e = blockIdx.x * blockDim.x + threadIdx.x;
    if (e >= E) return;
    int is64 = g_is64;
    int d = edge_at(ei, (long long)E + e, is64);   // dst half of edge_index
    atomicAdd(&g_deg[d], 1.0f);
}

__global__ void k_dinv(int n) {
    int i = blockIdx.x * blockDim.x + threadIdx.x;
    if (i < n) g_dinv[i] = rsqrtf(g_deg[i]);   // deg >= 1 always
}

// ---------------- GEMM: xw = x @ W1   [n,165] x [165,128] -------------------
// Tile: BM=64 rows x 128 cols, BK=16 (padded), 256 threads,
// each thread: 8 rows x 4 cols = 32 fp32 accumulators.
#define BM 64
#define BK 16
__global__ void __launch_bounds__(256) k_gemm1(const float* __restrict__ x,
                                               const float* __restrict__ W1,
                                               int n) {
    __shared__ float Xs[BM * BK];          // 4 KB
    __shared__ float Ws[BK * H1DIM];       // 8 KB
    const int tid = threadIdx.x;
    const int tn  = tid & 31;              // col group: cols tn*4 .. tn*4+3
    const int tw  = tid >> 5;              // warp id: rows tw*8 .. tw*8+7
    const int m0  = blockIdx.x * BM;

    float4 acc[8];
#pragma unroll
    for (int i = 0; i < 8; i++) acc[i] = make_float4(0.f, 0.f, 0.f, 0.f);

    const float4* W1v = (const float4*)W1;           // [165][32] float4
    float4* Wsv = (float4*)Ws;                       // [16][32] float4

    for (int kb = 0; kb < FDIM; kb += BK) {
        // load W tile: 16*128 floats = 512 float4; 2 per thread
#pragma unroll
        for (int j = 0; j < 2; j++) {
            int i = tid + j * 256;                   // 0..511
            int kg = kb + (i >> 5);
            int c4 = i & 31;
            Wsv[i] = (kg < FDIM) ? W1v[kg * 32 + c4]
                                 : make_float4(0.f, 0.f, 0.f, 0.f);
        }
        // load X tile: 64 rows x 16 k, one float4 per thread
        {
            int r   = tid >> 2;                      // 0..63
            int kk0 = (tid & 3) * 4;                 // 0,4,8,12
            int gm  = m0 + r;
            float4 xv = make_float4(0.f, 0.f, 0.f, 0.f);
            if (gm < n) {
                const float* xr = x + (long long)gm * FDIM + kb + kk0;
                float t[4];
#pragma unroll
                for (int j = 0; j < 4; j++) {
                    int kg = kb + kk0 + j;
                    t[j] = (kg < FDIM) ? xr[j] : 0.f;
                }
                xv = make_float4(t[0], t[1], t[2], t[3]);
            }
            *(float4*)&Xs[r * BK + kk0] = xv;
        }
        __syncthreads();

#pragma unroll
        for (int kk = 0; kk < BK; kk++) {
            float4 w = Wsv[kk * 32 + tn];
#pragma unroll
            for (int i = 0; i < 8; i++) {
                float xv = Xs[(tw * 8 + i) * BK + kk];   // warp broadcast
                acc[i].x += xv * w.x;
                acc[i].y += xv * w.y;
                acc[i].z += xv * w.z;
                acc[i].w += xv * w.w;
            }
        }
        __syncthreads();
    }

#pragma unroll
    for (int i = 0; i < 8; i++) {
        int gm = m0 + tw * 8 + i;
        if (gm < n)
            *(float4*)&g_xw[(long long)gm * H1DIM + tn * 4] = acc[i];
    }
}

// ---------------- scatter1: h1[dst] += xw[src] * norm -----------------------
// Warp handles EPW consecutive "edges" (incl. virtual self-loop edges at the
// tail): per edge, 32 lanes move one float4 each (128 floats = 512 B).
// Two edges in flight per warp doubles gather MLP.
#define EPW 2
__global__ void __launch_bounds__(512) k_scatter1(const void* __restrict__ ei,
                                                  int E, int n) {
    long long w = ((long long)blockIdx.x * blockDim.x + threadIdx.x) >> 5;
    int lane = threadIdx.x & 31;
    long long tot  = (long long)E + n;
    long long base = w * EPW;
    if (base >= tot) return;
    int is64 = g_is64;

    int s[EPW], d[EPW];
    float nrm[EPW];
#pragma unroll
    for (int j = 0; j < EPW; j++) {
        long long e = base + j;
        if (e >= tot) { s[j] = -1; continue; }
        if (e < E) {
            s[j] = edge_at(ei, e, is64);
            d[j] = edge_at(ei, (long long)E + e, is64);
            nrm[j] = __ldg(&g_dinv[s[j]]) * __ldg(&g_dinv[d[j]]);
        } else {
            s[j] = d[j] = (int)(e - E);
            float di = __ldg(&g_dinv[s[j]]);
            nrm[j] = di * di;
        }
    }
    // issue both gathers before either scatter (MLP)
    float4 v[EPW];
#pragma unroll
    for (int j = 0; j < EPW; j++)
        if (s[j] >= 0)
            v[j] = ((const float4*)&g_xw[(long long)s[j] * H1DIM])[lane];
#pragma unroll
    for (int j = 0; j < EPW; j++) {
        if (s[j] < 0) continue;
        float4 t = v[j];
        t.x *= nrm[j]; t.y *= nrm[j]; t.z *= nrm[j]; t.w *= nrm[j];
        red_add_v4(&g_h1[(long long)d[j] * H1DIM + lane * 4], t);
    }
}

// ---------------- layer2 transform: h2w = relu(h1+b1) @ W2  (warp/node) -----
__global__ void k_layer2(const float* __restrict__ b1,
                         const float* __restrict__ W2, int n) {
    int node = (int)(((long long)blockIdx.x * blockDim.x + threadIdx.x) >> 5);
    int lane = threadIdx.x & 31;
    if (node >= n) return;
    float4 v = ((const float4*)&g_h1[(long long)node * H1DIM])[lane];
    float4 b = ((const float4*)b1)[lane];
    v.x = fmaxf(v.x + b.x, 0.f);
    v.y = fmaxf(v.y + b.y, 0.f);
    v.z = fmaxf(v.z + b.z, 0.f);
    v.w = fmaxf(v.w + b.w, 0.f);
    // W2 is [128][2] row-major: lane covers rows lane*4 .. lane*4+3
    float4 wa = ((const float4*)W2)[lane * 2 + 0];   // rows l4+0, l4+1
    float4 wb = ((const float4*)W2)[lane * 2 + 1];   // rows l4+2, l4+3
    float a0 = v.x * wa.x + v.y * wa.z + v.z * wb.x + v.w * wb.z;
    float a1 = v.x * wa.y + v.y * wa.w + v.z * wb.y + v.w * wb.w;
#pragma unroll
    for (int off = 16; off > 0; off >>= 1) {
        a0 += __shfl_xor_sync(0xFFFFFFFFu, a0, off);
        a1 += __shfl_xor_sync(0xFFFFFFFFu, a1, off);
    }
    if (lane == 0) {
        g_h2w[(long long)node * 2 + 0] = a0;
        g_h2w[(long long)node * 2 + 1] = a1;
    }
}

// ---------------- scatter2: h2[dst] += h2w[src] * norm  (thread per edge) ---
__global__ void __launch_bounds__(512) k_scatter2(const void* __restrict__ ei,
                                                  int E, int n) {
    long long e = (long long)blockIdx.x * blockDim.x + threadIdx.x;
    long long tot = (long long)E + n;
    if (e >= tot) return;
    int is64 = g_is64;
    int s, d;
    float nrm;
    if (e < E) {
        s = edge_at(ei, e, is64);
        d = edge_at(ei, (long long)E + e, is64);
        nrm = __ldg(&g_dinv[s]) * __ldg(&g_dinv[d]);
    } else {
        s = d = (int)(e - E);
        float di = __ldg(&g_dinv[s]);
        nrm = di * di;
    }
    float2 v = *(const float2*)&g_h2w[(long long)s * 2];
    red_add_v2(&g_h2[(long long)d * 2], v.x * nrm, v.y * nrm);
}

// ---------------- head: out = sigmoid(relu(h2+b2) @ Wc + bc) ----------------
__global__ void k_head(const float* __restrict__ b2,
                       const float* __restrict__ Wc,
                       const float* __restrict__ bc,
                       float* __restrict__ out, int n) {
    int i = blockIdx.x * blockDim.x + threadIdx.x;
    if (i >= n) return;
    float z0 = fmaxf(g_h2[(long long)i * 2 + 0] + b2[0], 0.f);
    float z1 = fmaxf(g_h2[(long long)i * 2 + 1] + b2[1], 0.f);
    float o = z0 * Wc[0] + z1 * Wc[1] + bc[0];
    out[i] = 1.0f / (1.0f + __expf(-o));
}

// ----------------------------------------------------------------------------
extern "C" void kernel_launch(void* const* d_in, const int* in_sizes, int n_in,
                              void* d_out, int out_size) {
    const float* x   = (const float*)d_in[0];
    const void*  ei  = d_in[1];                  // int32 or int64, detected
    const float* W1  = (const float*)d_in[2];
    const float* b1  = (const float*)d_in[3];
    const float* W2  = (const float*)d_in[4];
    const float* b2  = (const float*)d_in[5];
    const float* Wc  = (const float*)d_in[6];
    const float* bc  = (const float*)d_in[7];
    float*       out = (float*)d_out;

    const int n = in_sizes[0] / FDIM;       // 100000
    const int E = in_sizes[1] / 2;          // 1600000

    const int T = 256;
    long long initN = (long long)n * H1DIM;
    k_init<<<(unsigned)((initN + T - 1) / T), T>>>((const int*)ei, n);
    k_degree<<<(E + T - 1) / T, T>>>(ei, E);
    k_dinv<<<(n + T - 1) / T, T>>>(n);
    k_gemm1<<<(n + BM - 1) / BM, 256>>>(x, W1, n);

    long long tot   = (long long)E + n;
    long long warps = (tot + EPW - 1) / EPW;
    long long thr1  = warps * 32;
    k_scatter1<<<(unsigned)((thr1 + 511) / 512), 512>>>(ei, E, n);

    long long thr2 = (long long)n * 32;
    k_layer2<<<(unsigned)((thr2 + T - 1) / T), T>>>(b1, W2, n);

    k_scatter2<<<(unsigned)((tot + 511) / 512), 512>>>(ei, E, n);
    k_head<<<(n + T - 1) / T, T>>>(b2, Wc, bc, out, n);
}